// round 8
// baseline (speedup 1.0000x reference)
#include <cuda_runtime.h>
#include <cuda_bf16.h>
#include <cstdint>

#define IMG_N_ANC   8649      // 31*31*9
#define PRE_NMS     6000
#define POST_NMS    1500
#define IOU_THR     0.7f
#define BATCH       16
#define NW          94        // 94 u64 words cover 6016 >= 6000 cols
#define NWP         96        // padded row stride (768 B)
#define NPAD        6016
#define NBIN        2048
#define NKEY        8704      // padded key capacity (>= 8649)

typedef unsigned long long u64;

// ---------------- device scratch (static; no allocations) ----------------
// row-major masks: g_masks[b][row][word]  (word w holds cols w*64..w*64+63)
__device__ u64   g_masks[BATCH][NPAD][NWP];   // ~73.9 MB
__device__ float g_y1[BATCH][NPAD];
__device__ float g_x1[BATCH][NPAD];
__device__ float g_y2[BATCH][NPAD];
__device__ float g_x2[BATCH][NPAD];
__device__ float g_ar[BATCH][NPAD];
__device__ float g_cs[BATCH][NPAD];           // ar * (0.7/1.7) for fast IoU test
__device__ float g_sc[BATCH][NPAD];

// ================= Kernel A: bucket sort + decode top-6000 =================
// Scores uniform [0,1): value-binned buckets are balanced (avg 4.2/bin).
// Exact ordering: bins monotone in score; within-bin insertion sort on the
// full u64 key (score bits || inverted index) == lax.top_k tie behavior.
#define A_NT          1024
#define A_OFF_RAW     0                              // u64 keys_raw[NKEY]
#define A_OFF_SORT    (NKEY * 8)                     // u64 keys_sorted[NKEY]
#define A_OFF_HIST    (A_OFF_SORT + NKEY * 8)        // u32 hist[NBIN]
#define A_OFF_START   (A_OFF_HIST + NBIN * 4)        // u32 start[NBIN]
#define A_SMEM_TOTAL  (A_OFF_START + NBIN * 4)       // ~155.6 KB

__global__ __launch_bounds__(A_NT, 1)
void sort_decode_kernel(const float* __restrict__ deltas,   // [B,N,4]
                        const float* __restrict__ probs,    // [B,N]
                        const float* __restrict__ anchors)  // [N,4]
{
    extern __shared__ char smem[];
    u64* keys_raw    = (u64*)(smem + A_OFF_RAW);
    u64* keys_sorted = (u64*)(smem + A_OFF_SORT);
    unsigned int* hist  = (unsigned int*)(smem + A_OFF_HIST);
    unsigned int* start = (unsigned int*)(smem + A_OFF_START);

    const int b   = blockIdx.x;
    const int tid = threadIdx.x;
    const int nt  = A_NT;

    for (int i = tid; i < NBIN; i += nt) hist[i] = 0u;
    __syncthreads();

    // pass 1: build keys + value-binned histogram
    const float* pb = probs + (size_t)b * IMG_N_ANC;
    for (int i = tid; i < IMG_N_ANC; i += nt) {
        float s = pb[i];
        unsigned int bits = __float_as_uint(s);       // [0,1): bit order == value order
        u64 k = ((u64)bits << 32) | (u64)(0xFFFFFFFFu - (unsigned)i);
        keys_raw[i] = k;
        int bin = (int)(s * (float)NBIN);
        bin = max(0, min(NBIN - 1, bin));
        atomicAdd(&hist[bin], 1u);
    }
    __syncthreads();

    // descending prefix scan: start[v] = #keys in bins > v  (one warp)
    if (tid < 32) {
        const int lane = tid;
        int part = 0;
        #pragma unroll 8
        for (int q = 0; q < 64; q++) part += (int)hist[NBIN - 1 - (lane * 64 + q)];
        int inc = part;
        #pragma unroll
        for (int off = 1; off < 32; off <<= 1) {
            int v = __shfl_up_sync(0xFFFFFFFFu, inc, off);
            if (lane >= off) inc += v;
        }
        int excl = inc - part;
        for (int q = 0; q < 64; q++) {
            int v = NBIN - 1 - (lane * 64 + q);
            start[v] = (unsigned int)excl;
            excl += (int)hist[v];
        }
    }
    __syncthreads();

    // reset hist -> per-bin scatter counters
    for (int i = tid; i < NBIN; i += nt) hist[i] = 0u;
    __syncthreads();

    // pass 2: scatter keys to bin segments
    for (int i = tid; i < IMG_N_ANC; i += nt) {
        u64 k = keys_raw[i];
        float s = __uint_as_float((unsigned int)(k >> 32));
        int bin = (int)(s * (float)NBIN);
        bin = max(0, min(NBIN - 1, bin));
        unsigned int pos = start[bin] + atomicAdd(&hist[bin], 1u);
        keys_sorted[pos] = k;
    }
    __syncthreads();

    // pass 3: per-bin insertion sort (descending, exact u64 keys)
    for (int v = tid; v < NBIN; v += nt) {
        int s0 = (int)start[v];
        int c  = (int)hist[v];
        if (s0 < PRE_NMS && c > 1) {
            for (int a = s0 + 1; a < s0 + c; a++) {
                u64 key = keys_sorted[a];
                int p = a - 1;
                while (p >= s0 && keys_sorted[p] < key) {
                    keys_sorted[p + 1] = keys_sorted[p];
                    p--;
                }
                keys_sorted[p + 1] = key;
            }
        }
    }
    __syncthreads();

    // pass 4: decode top-6000 to global SoA
    const float* db = deltas + (size_t)b * IMG_N_ANC * 4;
    for (int t = tid; t < PRE_NMS; t += nt) {
        u64 key = keys_sorted[t];
        unsigned int idx = 0xFFFFFFFFu - (unsigned int)(key & 0xFFFFFFFFull);
        float score = __uint_as_float((unsigned int)(key >> 32));

        float a0 = anchors[idx * 4 + 0];
        float a1 = anchors[idx * 4 + 1];
        float a2 = anchors[idx * 4 + 2];
        float a3 = anchors[idx * 4 + 3];
        float d0 = db[(size_t)idx * 4 + 0] * 0.1f;
        float d1 = db[(size_t)idx * 4 + 1] * 0.1f;
        float d2 = db[(size_t)idx * 4 + 2] * 0.2f;
        float d3 = db[(size_t)idx * 4 + 3] * 0.2f;

        float anc_h = a2 - a0;
        float anc_w = a3 - a1;
        float ctr_y = a0 + 0.5f * anc_h;
        float ctr_x = a1 + 0.5f * anc_w;
        float bh = expf(d2) * anc_h;
        float bw = expf(d3) * anc_w;
        float bcy = d0 * anc_h + ctr_y;
        float bcx = d1 * anc_w + ctr_x;
        float y1 = bcy - 0.5f * bh;
        float x1 = bcx - 0.5f * bw;
        float y2 = y1 + bh;
        float x2 = x1 + bw;

        float ar = (y2 - y1) * (x2 - x1);
        g_y1[b][t] = y1; g_x1[b][t] = x1;
        g_y2[b][t] = y2; g_x2[b][t] = x2;
        g_ar[b][t] = ar;
        g_cs[b][t] = ar * (IOU_THR / (1.0f + IOU_THR));
        g_sc[b][t] = score;
    }
}

// ================= Kernel B: forward suppression bit-matrix =================
// grid = (94 col_blocks, 12 row_blocks(512 rows), 16 batches), 64 threads.
// Each thread owns 8 rows. Fast test: inter > cs_i + cs_j (cs = 0.7/1.7*ar),
// with an absolute+relative band falling back to the exact reference chain.
__global__ __launch_bounds__(64)
void iou_matrix_kernel()
{
    const int cb = blockIdx.x;
    const int rb = blockIdx.y;
    if (cb < rb * 8) return;
    const int b   = blockIdx.z;
    const int tid = threadIdx.x;

    __shared__ float4 cbox[64];
    __shared__ float  ccs[64];
    __shared__ float  care[64];

    const int j0 = cb * 64;
    {
        int j = j0 + tid;
        if (j < PRE_NMS) {
            cbox[tid] = make_float4(g_y1[b][j], g_x1[b][j], g_y2[b][j], g_x2[b][j]);
            ccs[tid]  = g_cs[b][j];
            care[tid] = g_ar[b][j];
        } else {
            cbox[tid] = make_float4(0.f, 0.f, 0.f, 0.f);   // inter=0 -> never hits
            ccs[tid]  = 0.f;
            care[tid] = 0.f;
        }
    }
    __syncthreads();

    float ry1[8], rx1[8], ry2[8], rx2[8], rcs[8], rar[8];
    u64 bits[8];
    #pragma unroll
    for (int r = 0; r < 8; r++) {
        int i = rb * 512 + r * 64 + tid;
        int ii = (i < PRE_NMS) ? i : 0;
        ry1[r] = g_y1[b][ii]; rx1[r] = g_x1[b][ii];
        ry2[r] = g_y2[b][ii]; rx2[r] = g_x2[b][ii];
        rcs[r] = g_cs[b][ii]; rar[r] = g_ar[b][ii];
        bits[r] = 0ull;
    }

    #pragma unroll 4
    for (int j = 0; j < 64; j++) {
        float4 c4 = cbox[j];
        float  cc = ccs[j];
        #pragma unroll
        for (int r = 0; r < 8; r++) {
            float ih = fmaxf(fminf(ry2[r], c4.z) - fmaxf(ry1[r], c4.x), 0.0f);
            float iw = fmaxf(fminf(rx2[r], c4.w) - fmaxf(rx1[r], c4.y), 0.0f);
            float ssum = rcs[r] + cc;
            float diff = fmaf(ih, iw, -ssum);           // inter - 0.7/1.7*(ar_i+ar_j)
            bool hit = diff > 0.0f;
            float thr = fmaf(1e-4f, ssum, 1e-8f);       // rel band + abs floor
            if (fabsf(diff) <= thr) {                   // rare: exact reference chain
                float inter = __fmul_rn(ih, iw);
                float dd = __fadd_rn(__fadd_rn(__fadd_rn(rar[r], care[j]), -inter), 1e-8f);
                hit = __fdiv_rn(inter, dd) > IOU_THR;
            }
            if (hit) bits[r] |= (1ull << j);
        }
    }

    #pragma unroll
    for (int r = 0; r < 8; r++) {
        int i = rb * 512 + r * 64 + tid;
        // C only ever reads words cb >= i>>6
        if (i < PRE_NMS && cb >= (i >> 6)) {
            int dlt = i - j0;   // keep only cols j > i
            u64 m = (dlt < 0) ? ~0ull : ((dlt >= 63) ? 0ull : (~0ull << (dlt + 1)));
            g_masks[b][i][cb] = bits[r] & m;
        }
    }
}

// ================= Kernel C: greedy bit-reduce + output ====================
// 512 threads; 4-way co-owned suppression words (round-5 proven).
#define C_NT 512

__global__ __launch_bounds__(C_NT, 1)
void nms_reduce_kernel(float* __restrict__ out)
{
    const int b   = blockIdx.x;
    const int tid = threadIdx.x;

    __shared__ u64 s_diag[64];
    __shared__ u64 s_pub[4];
    __shared__ int s_rows[64];
    __shared__ int s_nk;

    float* ob = out + (size_t)b * POST_NMS * 4;
    float* os = out + (size_t)BATCH * POST_NMS * 4 + (size_t)b * POST_NMS;

    for (int t = tid; t < POST_NMS * 4; t += C_NT) ob[t] = 0.0f;
    for (int t = tid; t < POST_NMS; t += C_NT)     os[t] = 0.0f;

    const int w   = tid >> 2;        // owned word (valid when tid < 376)
    const int sub = tid & 3;
    u64 rem = 0ull;

    if (tid >= 448) s_diag[tid - 448] = g_masks[b][tid - 448][0];
    if (tid < 4) s_pub[tid] = 0ull;
    __syncthreads();

    int cnt = 0;
    for (int c = 0; c < NW; c++) {
        if (tid == 0) {
            u64 remc = s_pub[0] | s_pub[1] | s_pub[2] | s_pub[3];
            int lim = PRE_NMS - c * 64;             // >= 1 (94*64 = 6016 > 6000)
            u64 alive = ~remc;
            if (lim < 64) alive &= ((1ull << lim) - 1ull);
            int nk = 0, cc = cnt;
            while (alive && cc < POST_NMS) {
                int i = __ffsll((long long)alive) - 1;
                s_rows[nk++] = c * 64 + i;
                cc++;
                alive &= ~(s_diag[i] | (1ull << i));
            }
            s_nk = nk;
        }
        __syncthreads();
        const int nk = s_nk;

        if (tid < nk) {
            int r    = s_rows[tid];
            int rank = cnt + tid;
            ob[rank * 4 + 0] = fminf(fmaxf(g_y1[b][r], 0.0f), 1.0f);
            ob[rank * 4 + 1] = fminf(fmaxf(g_x1[b][r], 0.0f), 1.0f);
            ob[rank * 4 + 2] = fminf(fmaxf(g_y2[b][r], 0.0f), 1.0f);
            ob[rank * 4 + 3] = fminf(fmaxf(g_x2[b][r], 0.0f), 1.0f);
            os[rank] = g_sc[b][r];
        }

        if (tid < 376 && w > c) {
            #pragma unroll 4
            for (int m = sub; m < nk; m += 4) rem |= g_masks[b][s_rows[m]][w];
        }

        if (c + 1 < NW && tid >= 448) {
            int row = (c + 1) * 64 + (tid - 448);
            s_diag[tid - 448] = (row < PRE_NMS) ? g_masks[b][row][c + 1] : 0ull;
        }

        if (tid < 376 && w == c + 1) s_pub[sub] = rem;

        cnt += nk;
        __syncthreads();
        if (cnt >= POST_NMS) break;
    }
}

// ============================== launch =====================================
extern "C" void kernel_launch(void* const* d_in, const int* in_sizes, int n_in,
                              void* d_out, int out_size) {
    const float* deltas  = (const float*)d_in[0];  // [16,31,31,36]
    const float* probs   = (const float*)d_in[1];  // [16,31,31,9]
    const float* anchors = (const float*)d_in[2];  // [8649,4]
    float* out = (float*)d_out;

    cudaFuncSetAttribute(sort_decode_kernel,
                         cudaFuncAttributeMaxDynamicSharedMemorySize, A_SMEM_TOTAL);

    sort_decode_kernel<<<BATCH, A_NT, A_SMEM_TOTAL>>>(deltas, probs, anchors);
    iou_matrix_kernel<<<dim3(NW, 12, BATCH), 64>>>();
    nms_reduce_kernel<<<BATCH, C_NT>>>(out);
}

// round 9
// speedup vs baseline: 1.1690x; 1.1690x over previous
#include <cuda_runtime.h>
#include <cuda_bf16.h>
#include <cstdint>

#define IMG_N_ANC   8649      // 31*31*9
#define PRE_NMS     6000
#define POST_NMS    1500
#define IOU_THR     0.7f
#define BATCH       16
#define NW          94        // 94 u64 words cover 6016 >= 6000 cols
#define NWP         96        // padded row stride (768 B)
#define NPAD        6016
#define NBIN        2048
#define NKEY        8704      // padded key capacity (>= 8649)

typedef unsigned long long u64;

// ---------------- device scratch (static; no allocations) ----------------
__device__ u64   g_masks[BATCH][NPAD][NWP];   // [b][row][word], ~73.9 MB
__device__ float g_y1[BATCH][NPAD];
__device__ float g_x1[BATCH][NPAD];
__device__ float g_y2[BATCH][NPAD];
__device__ float g_x2[BATCH][NPAD];
__device__ float g_ar[BATCH][NPAD];
__device__ float g_cs[BATCH][NPAD];           // ar * (0.7/1.7)
__device__ float g_sc[BATCH][NPAD];

// ================= Kernel A: bucket sort + decode top-6000 =================
#define A_NT          1024
#define A_OFF_RAW     0
#define A_OFF_SORT    (NKEY * 8)
#define A_OFF_HIST    (A_OFF_SORT + NKEY * 8)
#define A_OFF_START   (A_OFF_HIST + NBIN * 4)
#define A_SMEM_TOTAL  (A_OFF_START + NBIN * 4)

__global__ __launch_bounds__(A_NT, 1)
void sort_decode_kernel(const float* __restrict__ deltas,
                        const float* __restrict__ probs,
                        const float* __restrict__ anchors)
{
    extern __shared__ char smem[];
    u64* keys_raw    = (u64*)(smem + A_OFF_RAW);
    u64* keys_sorted = (u64*)(smem + A_OFF_SORT);
    unsigned int* hist  = (unsigned int*)(smem + A_OFF_HIST);
    unsigned int* start = (unsigned int*)(smem + A_OFF_START);

    const int b   = blockIdx.x;
    const int tid = threadIdx.x;
    const int nt  = A_NT;

    for (int i = tid; i < NBIN; i += nt) hist[i] = 0u;
    __syncthreads();

    const float* pb = probs + (size_t)b * IMG_N_ANC;
    for (int i = tid; i < IMG_N_ANC; i += nt) {
        float s = pb[i];
        unsigned int bits = __float_as_uint(s);
        u64 k = ((u64)bits << 32) | (u64)(0xFFFFFFFFu - (unsigned)i);
        keys_raw[i] = k;
        int bin = (int)(s * (float)NBIN);
        bin = max(0, min(NBIN - 1, bin));
        atomicAdd(&hist[bin], 1u);
    }
    __syncthreads();

    if (tid < 32) {
        const int lane = tid;
        int part = 0;
        #pragma unroll 8
        for (int q = 0; q < 64; q++) part += (int)hist[NBIN - 1 - (lane * 64 + q)];
        int inc = part;
        #pragma unroll
        for (int off = 1; off < 32; off <<= 1) {
            int v = __shfl_up_sync(0xFFFFFFFFu, inc, off);
            if (lane >= off) inc += v;
        }
        int excl = inc - part;
        for (int q = 0; q < 64; q++) {
            int v = NBIN - 1 - (lane * 64 + q);
            start[v] = (unsigned int)excl;
            excl += (int)hist[v];
        }
    }
    __syncthreads();

    for (int i = tid; i < NBIN; i += nt) hist[i] = 0u;
    __syncthreads();

    for (int i = tid; i < IMG_N_ANC; i += nt) {
        u64 k = keys_raw[i];
        float s = __uint_as_float((unsigned int)(k >> 32));
        int bin = (int)(s * (float)NBIN);
        bin = max(0, min(NBIN - 1, bin));
        unsigned int pos = start[bin] + atomicAdd(&hist[bin], 1u);
        keys_sorted[pos] = k;
    }
    __syncthreads();

    for (int v = tid; v < NBIN; v += nt) {
        int s0 = (int)start[v];
        int c  = (int)hist[v];
        if (s0 < PRE_NMS && c > 1) {
            for (int a = s0 + 1; a < s0 + c; a++) {
                u64 key = keys_sorted[a];
                int p = a - 1;
                while (p >= s0 && keys_sorted[p] < key) {
                    keys_sorted[p + 1] = keys_sorted[p];
                    p--;
                }
                keys_sorted[p + 1] = key;
            }
        }
    }
    __syncthreads();

    const float* db = deltas + (size_t)b * IMG_N_ANC * 4;
    for (int t = tid; t < PRE_NMS; t += nt) {
        u64 key = keys_sorted[t];
        unsigned int idx = 0xFFFFFFFFu - (unsigned int)(key & 0xFFFFFFFFull);
        float score = __uint_as_float((unsigned int)(key >> 32));

        float a0 = anchors[idx * 4 + 0];
        float a1 = anchors[idx * 4 + 1];
        float a2 = anchors[idx * 4 + 2];
        float a3 = anchors[idx * 4 + 3];
        float d0 = db[(size_t)idx * 4 + 0] * 0.1f;
        float d1 = db[(size_t)idx * 4 + 1] * 0.1f;
        float d2 = db[(size_t)idx * 4 + 2] * 0.2f;
        float d3 = db[(size_t)idx * 4 + 3] * 0.2f;

        float anc_h = a2 - a0;
        float anc_w = a3 - a1;
        float ctr_y = a0 + 0.5f * anc_h;
        float ctr_x = a1 + 0.5f * anc_w;
        float bh = expf(d2) * anc_h;
        float bw = expf(d3) * anc_w;
        float bcy = d0 * anc_h + ctr_y;
        float bcx = d1 * anc_w + ctr_x;
        float y1 = bcy - 0.5f * bh;
        float x1 = bcx - 0.5f * bw;
        float y2 = y1 + bh;
        float x2 = x1 + bw;

        float ar = (y2 - y1) * (x2 - x1);
        g_y1[b][t] = y1; g_x1[b][t] = x1;
        g_y2[b][t] = y2; g_x2[b][t] = x2;
        g_ar[b][t] = ar;
        g_cs[b][t] = ar * (IOU_THR / (1.0f + IOU_THR));
        g_sc[b][t] = score;
    }
}

// ================= Kernel B: forward suppression bit-matrix =================
// Geometry identical to the proven round-5/7 version: grid (94, 24, 16),
// 64 threads, 4 rows/thread. Only the per-pair arithmetic is leaner:
//   fast hit:  fma(ih, iw, -(cs_i+cs_j)) > 0
//   band:      |diff| <= 1e-4*ssum + 1e-8  -> exact reference chain post-loop
//   bits:      u32 shift-accumulate (j descending), no 64-bit variable shifts
__device__ __forceinline__ bool iou_exact_hit(float ry1, float rx1, float ry2,
                                              float rx2, float rar,
                                              float4 c4, float ca)
{
    float ih = fmaxf(fminf(ry2, c4.z) - fmaxf(ry1, c4.x), 0.0f);
    float iw = fmaxf(fminf(rx2, c4.w) - fmaxf(rx1, c4.y), 0.0f);
    float inter = __fmul_rn(ih, iw);
    float dd = __fadd_rn(__fadd_rn(__fadd_rn(rar, ca), -inter), 1e-8f);
    return __fdiv_rn(inter, dd) > IOU_THR;
}

__global__ __launch_bounds__(64)
void iou_matrix_kernel()
{
    const int cb = blockIdx.x;
    const int rb = blockIdx.y;
    if (cb < rb * 4) return;
    const int b   = blockIdx.z;
    const int tid = threadIdx.x;

    __shared__ float4 cbox[64];
    __shared__ float  cncs[64];    // -cs of column
    __shared__ float  care[64];    // exact area (fallback only)

    const int j0 = cb * 64;
    {
        int j = j0 + tid;
        if (j < PRE_NMS) {
            cbox[tid] = make_float4(g_y1[b][j], g_x1[b][j], g_y2[b][j], g_x2[b][j]);
            cncs[tid] = -g_cs[b][j];
            care[tid] = g_ar[b][j];
        } else {
            cbox[tid] = make_float4(0.f, 0.f, 0.f, 0.f);   // inter=0 -> never hits
            cncs[tid] = 0.f;
            care[tid] = 0.f;
        }
    }
    __syncthreads();

    float ry1[4], rx1[4], ry2[4], rx2[4], rncs[4], rar[4];
    #pragma unroll
    for (int r = 0; r < 4; r++) {
        int i = rb * 256 + r * 64 + tid;
        int ii = (i < PRE_NMS) ? i : 0;
        ry1[r] = g_y1[b][ii]; rx1[r] = g_x1[b][ii];
        ry2[r] = g_y2[b][ii]; rx2[r] = g_x2[b][ii];
        rncs[r] = -g_cs[b][ii]; rar[r] = g_ar[b][ii];
    }

    unsigned int bhi[4] = {0,0,0,0}, blo[4] = {0,0,0,0};
    unsigned int fhi[4] = {0,0,0,0}, flo[4] = {0,0,0,0};

    // j = 63 .. 32  (shift-accumulate into hi words)
    #pragma unroll 8
    for (int j = 63; j >= 32; j--) {
        float4 c4 = cbox[j];
        float ncc = cncs[j];
        #pragma unroll
        for (int r = 0; r < 4; r++) {
            float ih = fmaxf(fminf(ry2[r], c4.z) - fmaxf(ry1[r], c4.x), 0.0f);
            float iw = fmaxf(fminf(rx2[r], c4.w) - fmaxf(rx1[r], c4.y), 0.0f);
            float nss  = rncs[r] + ncc;                // -(cs_i + cs_j)
            float diff = fmaf(ih, iw, nss);            // inter - ssum
            float nthr = fmaf(1e-4f, nss, -1e-8f);     // -(1e-4*ssum + 1e-8)
            float t    = fabsf(diff) + nthr;           // <= 0 -> in band
            bhi[r] = (bhi[r] << 1) | (diff > 0.0f ? 1u : 0u);
            fhi[r] = (fhi[r] << 1) | (t <= 0.0f ? 1u : 0u);
        }
    }
    // j = 31 .. 0
    #pragma unroll 8
    for (int j = 31; j >= 0; j--) {
        float4 c4 = cbox[j];
        float ncc = cncs[j];
        #pragma unroll
        for (int r = 0; r < 4; r++) {
            float ih = fmaxf(fminf(ry2[r], c4.z) - fmaxf(ry1[r], c4.x), 0.0f);
            float iw = fmaxf(fminf(rx2[r], c4.w) - fmaxf(rx1[r], c4.y), 0.0f);
            float nss  = rncs[r] + ncc;
            float diff = fmaf(ih, iw, nss);
            float nthr = fmaf(1e-4f, nss, -1e-8f);
            float t    = fabsf(diff) + nthr;
            blo[r] = (blo[r] << 1) | (diff > 0.0f ? 1u : 0u);
            flo[r] = (flo[r] << 1) | (t <= 0.0f ? 1u : 0u);
        }
    }

    // rare: resolve in-band pairs with the exact reference arithmetic
    #pragma unroll
    for (int r = 0; r < 4; r++) {
        unsigned int f = flo[r];
        while (f) {
            int j = __ffs(f) - 1; f &= f - 1u;
            bool hit = iou_exact_hit(ry1[r], rx1[r], ry2[r], rx2[r], rar[r],
                                     cbox[j], care[j]);
            blo[r] = hit ? (blo[r] | (1u << j)) : (blo[r] & ~(1u << j));
        }
        f = fhi[r];
        while (f) {
            int j = __ffs(f) - 1; f &= f - 1u;
            bool hit = iou_exact_hit(ry1[r], rx1[r], ry2[r], rx2[r], rar[r],
                                     cbox[j + 32], care[j + 32]);
            bhi[r] = hit ? (bhi[r] | (1u << j)) : (bhi[r] & ~(1u << j));
        }
    }

    #pragma unroll
    for (int r = 0; r < 4; r++) {
        int i = rb * 256 + r * 64 + tid;
        if (i < PRE_NMS && cb >= (i >> 6)) {           // C never reads cb < i>>6
            u64 bits = ((u64)bhi[r] << 32) | (u64)blo[r];
            int dlt = i - j0;                          // keep only cols j > i
            u64 m = (dlt < 0) ? ~0ull : ((dlt >= 63) ? 0ull : (~0ull << (dlt + 1)));
            g_masks[b][i][cb] = bits & m;
        }
    }
}

// ================= Kernel C: greedy bit-reduce + output ====================
#define C_NT 512

__global__ __launch_bounds__(C_NT, 1)
void nms_reduce_kernel(float* __restrict__ out)
{
    const int b   = blockIdx.x;
    const int tid = threadIdx.x;

    __shared__ u64 s_diag[64];
    __shared__ u64 s_pub[4];
    __shared__ int s_rows[64];
    __shared__ int s_nk;

    float* ob = out + (size_t)b * POST_NMS * 4;
    float* os = out + (size_t)BATCH * POST_NMS * 4 + (size_t)b * POST_NMS;

    for (int t = tid; t < POST_NMS * 4; t += C_NT) ob[t] = 0.0f;
    for (int t = tid; t < POST_NMS; t += C_NT)     os[t] = 0.0f;

    const int w   = tid >> 2;        // owned word (valid when tid < 376)
    const int sub = tid & 3;
    u64 rem = 0ull;

    if (tid >= 448) s_diag[tid - 448] = g_masks[b][tid - 448][0];
    if (tid < 4) s_pub[tid] = 0ull;
    __syncthreads();

    int cnt = 0;
    for (int c = 0; c < NW; c++) {
        if (tid == 0) {
            u64 remc = s_pub[0] | s_pub[1] | s_pub[2] | s_pub[3];
            int lim = PRE_NMS - c * 64;
            u64 alive = ~remc;
            if (lim < 64) alive &= ((1ull << lim) - 1ull);
            int nk = 0, cc = cnt;
            while (alive && cc < POST_NMS) {
                int i = __ffsll((long long)alive) - 1;
                s_rows[nk++] = c * 64 + i;
                cc++;
                alive &= ~(s_diag[i] | (1ull << i));
            }
            s_nk = nk;
        }
        __syncthreads();
        const int nk = s_nk;

        if (tid < nk) {
            int r    = s_rows[tid];
            int rank = cnt + tid;
            ob[rank * 4 + 0] = fminf(fmaxf(g_y1[b][r], 0.0f), 1.0f);
            ob[rank * 4 + 1] = fminf(fmaxf(g_x1[b][r], 0.0f), 1.0f);
            ob[rank * 4 + 2] = fminf(fmaxf(g_y2[b][r], 0.0f), 1.0f);
            ob[rank * 4 + 3] = fminf(fmaxf(g_x2[b][r], 0.0f), 1.0f);
            os[rank] = g_sc[b][r];
        }

        if (tid < 376 && w > c) {
            #pragma unroll 4
            for (int m = sub; m < nk; m += 4) rem |= g_masks[b][s_rows[m]][w];
        }

        if (c + 1 < NW && tid >= 448) {
            int row = (c + 1) * 64 + (tid - 448);
            s_diag[tid - 448] = (row < PRE_NMS) ? g_masks[b][row][c + 1] : 0ull;
        }

        if (tid < 376 && w == c + 1) s_pub[sub] = rem;

        cnt += nk;
        __syncthreads();
        if (cnt >= POST_NMS) break;
    }
}

// ============================== launch =====================================
extern "C" void kernel_launch(void* const* d_in, const int* in_sizes, int n_in,
                              void* d_out, int out_size) {
    const float* deltas  = (const float*)d_in[0];
    const float* probs   = (const float*)d_in[1];
    const float* anchors = (const float*)d_in[2];
    float* out = (float*)d_out;

    cudaFuncSetAttribute(sort_decode_kernel,
                         cudaFuncAttributeMaxDynamicSharedMemorySize, A_SMEM_TOTAL);

    sort_decode_kernel<<<BATCH, A_NT, A_SMEM_TOTAL>>>(deltas, probs, anchors);
    iou_matrix_kernel<<<dim3(NW, 24, BATCH), 64>>>();
    nms_reduce_kernel<<<BATCH, C_NT>>>(out);
}